// round 1
// baseline (speedup 1.0000x reference)
#include <cuda_runtime.h>

// Idx2PixelLayer: bilinear gather
//   coords : (N, 2) float32      (d_in[0])
//   visible: (2048, 2048, 8) f32 (d_in[1])
//   out    : (N, 8) float32
//
// c = (coords - 1) mod (dims - 4) + 1 ; i = floor(c); d = c - i
// tl=g(0,0) tr=g(+1row,0) bl=g(0,+1col) br=g(+1row,+1col)
// mb = br + d0*(bl-br); mt = tr + d0*(tl-tr); out = mb + d1*(mt-mb)
// (off/where branch is dead: c in [1,2045) <= 2048)

#define HW 2048
#define CCH 8

__global__ __launch_bounds__(256) void idx2pixel_kernel(
    const float* __restrict__ coords,
    const float* __restrict__ vis,
    float* __restrict__ out,
    int n)
{
    int t = blockIdx.x * blockDim.x + threadIdx.x;
    if (t >= n) return;

    float2 xy = reinterpret_cast<const float2*>(coords)[t];
    const float M = (float)(HW - 4);   // 2044

    float c0 = fmodf(xy.x - 1.0f, M); if (c0 < 0.0f) c0 += M; c0 += 1.0f;
    float c1 = fmodf(xy.y - 1.0f, M); if (c1 < 0.0f) c1 += M; c1 += 1.0f;

    float f0 = floorf(c0);
    float f1 = floorf(c1);
    float d0 = c0 - f0;
    float d1 = c1 - f1;
    int i0 = (int)f0;   // row
    int i1 = (int)f1;   // col

    // row i0 holds tl (col i1) and bl (col i1+1); row i0+1 holds tr and br.
    const float4* r0 = reinterpret_cast<const float4*>(vis + ((size_t)i0 * HW + i1) * CCH);
    const float4* r1 = reinterpret_cast<const float4*>(vis + ((size_t)(i0 + 1) * HW + i1) * CCH);

    float4 tl_a = __ldg(r0 + 0), tl_b = __ldg(r0 + 1);
    float4 bl_a = __ldg(r0 + 2), bl_b = __ldg(r0 + 3);
    float4 tr_a = __ldg(r1 + 0), tr_b = __ldg(r1 + 1);
    float4 br_a = __ldg(r1 + 2), br_b = __ldg(r1 + 3);

    float4 o_a, o_b;
    {
        // component-wise: mb = br + d0*(bl-br); mt = tr + d0*(tl-tr); o = mb + d1*(mt-mb)
        float mb, mt;
        mb = br_a.x + d0 * (bl_a.x - br_a.x); mt = tr_a.x + d0 * (tl_a.x - tr_a.x); o_a.x = mb + d1 * (mt - mb);
        mb = br_a.y + d0 * (bl_a.y - br_a.y); mt = tr_a.y + d0 * (tl_a.y - tr_a.y); o_a.y = mb + d1 * (mt - mb);
        mb = br_a.z + d0 * (bl_a.z - br_a.z); mt = tr_a.z + d0 * (tl_a.z - tr_a.z); o_a.z = mb + d1 * (mt - mb);
        mb = br_a.w + d0 * (bl_a.w - br_a.w); mt = tr_a.w + d0 * (tl_a.w - tr_a.w); o_a.w = mb + d1 * (mt - mb);
        mb = br_b.x + d0 * (bl_b.x - br_b.x); mt = tr_b.x + d0 * (tl_b.x - tr_b.x); o_b.x = mb + d1 * (mt - mb);
        mb = br_b.y + d0 * (bl_b.y - br_b.y); mt = tr_b.y + d0 * (tl_b.y - tr_b.y); o_b.y = mb + d1 * (mt - mb);
        mb = br_b.z + d0 * (bl_b.z - br_b.z); mt = tr_b.z + d0 * (tl_b.z - tr_b.z); o_b.z = mb + d1 * (mt - mb);
        mb = br_b.w + d0 * (bl_b.w - br_b.w); mt = tr_b.w + d0 * (tl_b.w - tr_b.w); o_b.w = mb + d1 * (mt - mb);
    }

    // off = c > 2048 is never true (c < 2045), so no zeroing needed.
    float4* op = reinterpret_cast<float4*>(out) + (size_t)t * 2;
    op[0] = o_a;
    op[1] = o_b;
}

extern "C" void kernel_launch(void* const* d_in, const int* in_sizes, int n_in,
                              void* d_out, int out_size)
{
    const float* coords = (const float*)d_in[0];
    const float* vis    = (const float*)d_in[1];
    float* out          = (float*)d_out;

    int n = in_sizes[0] / 2;   // coords has N*2 elements
    int threads = 256;
    int blocks = (n + threads - 1) / threads;
    idx2pixel_kernel<<<blocks, threads>>>(coords, vis, out, n);
}

// round 2
// speedup vs baseline: 1.1437x; 1.1437x over previous
#include <cuda_runtime.h>

// Idx2PixelLayer: bilinear gather, cooperative 4-lanes-per-point layout.
//   coords : (N, 2) float32      (d_in[0])
//   visible: (2048, 2048, 8) f32 (d_in[1])
//   out    : (N, 8) float32
//
// Each point needs two 64B row-segments:
//   row i0  : [tl (32B ch0-7) | bl (32B)]
//   row i0+1: [tr (32B)       | br (32B)]
// Lane j (j=0..3 within group) loads 16B at +16j from each row base.
//   j=0: tl ch0-3 / tr ch0-3     j=1: tl ch4-7 / tr ch4-7
//   j=2: bl ch0-3 / br ch0-3     j=3: bl ch4-7 / br ch4-7
// v = B + d0*(A-B)  gives mt on lanes 0,1 and mb on lanes 2,3.
// shfl_xor(2) exchanges mt<->mb; out = mb + d1*(mt-mb). Lanes 0,1 store.

#define HW 2048
#define CCH 8

__global__ __launch_bounds__(256) void idx2pixel_coop_kernel(
    const float* __restrict__ coords,
    const float* __restrict__ vis,
    float* __restrict__ out,
    int n)
{
    int gtid  = blockIdx.x * blockDim.x + threadIdx.x;
    int w     = gtid >> 5;            // global warp id
    int lane  = threadIdx.x & 31;
    int group = lane >> 2;            // 0..7
    int j     = lane & 3;             // 0..3 within group
    int point = w * 8 + group;
    if (point >= n) return;

    unsigned mask = __activemask();

    float2 xy = reinterpret_cast<const float2*>(coords)[point];
    const float M = (float)(HW - 4);   // 2044

    float c0 = fmodf(xy.x - 1.0f, M); if (c0 < 0.0f) c0 += M; c0 += 1.0f;
    float c1 = fmodf(xy.y - 1.0f, M); if (c1 < 0.0f) c1 += M; c1 += 1.0f;

    float f0 = floorf(c0);
    float f1 = floorf(c1);
    float d0 = c0 - f0;
    float d1 = c1 - f1;
    int i0 = (int)f0;   // row
    int i1 = (int)f1;   // col

    // 64B segment base for row i0 (tl|bl) and row i0+1 (tr|br); lane offset 16B*j.
    const float* baseA = vis + ((size_t)i0 * HW + i1) * CCH + j * 4;
    const float* baseB = baseA + (size_t)HW * CCH;   // next row, +64KB

    float4 A = __ldg(reinterpret_cast<const float4*>(baseA));  // tl/bl half
    float4 B = __ldg(reinterpret_cast<const float4*>(baseB));  // tr/br half

    // v = B + d0*(A - B):  lanes 0,1 -> mt = tr + d0*(tl-tr)
    //                      lanes 2,3 -> mb = br + d0*(bl-br)
    float4 v;
    v.x = B.x + d0 * (A.x - B.x);
    v.y = B.y + d0 * (A.y - B.y);
    v.z = B.z + d0 * (A.z - B.z);
    v.w = B.w + d0 * (A.w - B.w);

    // Exchange mt <-> mb between lane pairs (0<->2, 1<->3).
    float4 o;
    o.x = __shfl_xor_sync(mask, v.x, 2);
    o.y = __shfl_xor_sync(mask, v.y, 2);
    o.z = __shfl_xor_sync(mask, v.z, 2);
    o.w = __shfl_xor_sync(mask, v.w, 2);

    // mt on lanes 0,1 is v; mb is o.  out = mb + d1*(mt - mb)
    float4 mt, mb;
    if (j < 2) { mt = v; mb = o; } else { mt = o; mb = v; }

    float4 r;
    r.x = mb.x + d1 * (mt.x - mb.x);
    r.y = mb.y + d1 * (mt.y - mb.y);
    r.z = mb.z + d1 * (mt.z - mb.z);
    r.w = mb.w + d1 * (mt.w - mb.w);

    // off = c > 2048 never true (c < 2045): no zeroing needed.
    if (j < 2) {
        reinterpret_cast<float4*>(out)[(size_t)point * 2 + j] = r;
    }
}

extern "C" void kernel_launch(void* const* d_in, const int* in_sizes, int n_in,
                              void* d_out, int out_size)
{
    const float* coords = (const float*)d_in[0];
    const float* vis    = (const float*)d_in[1];
    float* out          = (float*)d_out;

    int n = in_sizes[0] / 2;            // number of points
    int threads = 256;                   // 8 warps -> 64 points per block
    int points_per_block = (threads / 32) * 8;
    int blocks = (n + points_per_block - 1) / points_per_block;
    idx2pixel_coop_kernel<<<blocks, threads>>>(coords, vis, out, n);
}

// round 4
// speedup vs baseline: 1.2933x; 1.1308x over previous
#include <cuda_runtime.h>

// Idx2PixelLayer bilinear gather — cooperative 4-lanes-per-point, 2 points per
// lane-group, L2 policy segregation via createpolicy + cache_hint:
//   visible : ld.global.nc.L2::cache_hint (evict_last policy; array ~= L2 size)
//   coords  : ld.global.cs                 (streaming)
//   out     : st.global.cs                 (streaming, no L2 pollution)

#define HW 2048
#define CCH 8

__device__ __forceinline__ unsigned long long mk_policy_el() {
    unsigned long long p;
    asm("createpolicy.fractional.L2::evict_last.b64 %0, 1.0;" : "=l"(p));
    return p;
}

__device__ __forceinline__ float4 ldg_vis(const float* p, unsigned long long pol) {
    float4 v;
    asm volatile("ld.global.nc.L2::cache_hint.v4.f32 {%0,%1,%2,%3}, [%4], %5;"
                 : "=f"(v.x), "=f"(v.y), "=f"(v.z), "=f"(v.w)
                 : "l"(p), "l"(pol));
    return v;
}

__device__ __forceinline__ float4 ldg_stream4(const float* p) {
    float4 v;
    asm volatile("ld.global.cs.v4.f32 {%0,%1,%2,%3}, [%4];"
                 : "=f"(v.x), "=f"(v.y), "=f"(v.z), "=f"(v.w) : "l"(p));
    return v;
}

__device__ __forceinline__ void stg_stream4(float* p, float4 v) {
    asm volatile("st.global.cs.v4.f32 [%0], {%1,%2,%3,%4};"
                 :: "l"(p), "f"(v.x), "f"(v.y), "f"(v.z), "f"(v.w) : "memory");
}

__global__ __launch_bounds__(256) void idx2pixel_coop2_kernel(
    const float* __restrict__ coords,
    const float* __restrict__ vis,
    float* __restrict__ out,
    int n)
{
    int gtid  = blockIdx.x * blockDim.x + threadIdx.x;
    int w     = gtid >> 5;            // global warp id
    int lane  = threadIdx.x & 31;
    int group = lane >> 2;            // 0..7
    int j     = lane & 3;             // 0..3 within group
    int pbase = (w * 8 + group) * 2;  // first of the point pair
    if (pbase >= n) return;

    unsigned mask = __activemask();
    unsigned long long pol = mk_policy_el();
    const float M = (float)(HW - 4);   // 2044

    // Two points' coords in one 16B load: (x0, y0, x1, y1)
    float4 cxy = ldg_stream4(coords + (size_t)pbase * 2);

    // ---- address math for both points ----
    float c0a = fmodf(cxy.x - 1.0f, M); if (c0a < 0.0f) c0a += M; c0a += 1.0f;
    float c1a = fmodf(cxy.y - 1.0f, M); if (c1a < 0.0f) c1a += M; c1a += 1.0f;
    float c0b = fmodf(cxy.z - 1.0f, M); if (c0b < 0.0f) c0b += M; c0b += 1.0f;
    float c1b = fmodf(cxy.w - 1.0f, M); if (c1b < 0.0f) c1b += M; c1b += 1.0f;

    float f0a = floorf(c0a), f1a = floorf(c1a);
    float f0b = floorf(c0b), f1b = floorf(c1b);
    float d0a = c0a - f0a, d1a = c1a - f1a;
    float d0b = c0b - f0b, d1b = c1b - f1b;
    int i0a = (int)f0a, i1a = (int)f1a;
    int i0b = (int)f0b, i1b = (int)f1b;

    const float* pa0 = vis + ((size_t)i0a * HW + i1a) * CCH + j * 4;
    const float* pa1 = pa0 + (size_t)HW * CCH;
    const float* pb0 = vis + ((size_t)i0b * HW + i1b) * CCH + j * 4;
    const float* pb1 = pb0 + (size_t)HW * CCH;

    // ---- 4 gather loads in flight ----
    float4 Aa = ldg_vis(pa0, pol);   // point a: tl/bl half (row i0)
    float4 Ba = ldg_vis(pa1, pol);   // point a: tr/br half (row i0+1)
    float4 Ab = ldg_vis(pb0, pol);
    float4 Bb = ldg_vis(pb1, pol);

    // v = B + d0*(A-B): lanes 0,1 -> mt ; lanes 2,3 -> mb
    float4 va, vb;
    va.x = Ba.x + d0a * (Aa.x - Ba.x);
    va.y = Ba.y + d0a * (Aa.y - Ba.y);
    va.z = Ba.z + d0a * (Aa.z - Ba.z);
    va.w = Ba.w + d0a * (Aa.w - Ba.w);
    vb.x = Bb.x + d0b * (Ab.x - Bb.x);
    vb.y = Bb.y + d0b * (Ab.y - Bb.y);
    vb.z = Bb.z + d0b * (Ab.z - Bb.z);
    vb.w = Bb.w + d0b * (Ab.w - Bb.w);

    // exchange mt <-> mb between lane pairs (xor 2)
    float4 oa, ob;
    oa.x = __shfl_xor_sync(mask, va.x, 2);
    oa.y = __shfl_xor_sync(mask, va.y, 2);
    oa.z = __shfl_xor_sync(mask, va.z, 2);
    oa.w = __shfl_xor_sync(mask, va.w, 2);
    ob.x = __shfl_xor_sync(mask, vb.x, 2);
    ob.y = __shfl_xor_sync(mask, vb.y, 2);
    ob.z = __shfl_xor_sync(mask, vb.z, 2);
    ob.w = __shfl_xor_sync(mask, vb.w, 2);

    float4 mta, mba, mtb, mbb;
    if (j < 2) { mta = va; mba = oa; mtb = vb; mbb = ob; }
    else       { mta = oa; mba = va; mtb = ob; mbb = vb; }

    float4 ra, rb;
    ra.x = mba.x + d1a * (mta.x - mba.x);
    ra.y = mba.y + d1a * (mta.y - mba.y);
    ra.z = mba.z + d1a * (mta.z - mba.z);
    ra.w = mba.w + d1a * (mta.w - mba.w);
    rb.x = mbb.x + d1b * (mtb.x - mbb.x);
    rb.y = mbb.y + d1b * (mtb.y - mbb.y);
    rb.z = mbb.z + d1b * (mtb.z - mbb.z);
    rb.w = mbb.w + d1b * (mtb.w - mbb.w);

    // off = c > 2048 never true (c in [1, 2045)): no zeroing.
    if (j < 2) {
        stg_stream4(out + ((size_t)pbase * CCH) + j * 4, ra);
        if (pbase + 1 < n)
            stg_stream4(out + ((size_t)(pbase + 1) * CCH) + j * 4, rb);
    }
}

extern "C" void kernel_launch(void* const* d_in, const int* in_sizes, int n_in,
                              void* d_out, int out_size)
{
    const float* coords = (const float*)d_in[0];
    const float* vis    = (const float*)d_in[1];
    float* out          = (float*)d_out;

    int n = in_sizes[0] / 2;             // number of points
    int threads = 256;                    // 8 warps -> 8*8*2 = 128 points/block
    int ppb = (threads / 32) * 8 * 2;
    int blocks = (n + ppb - 1) / ppb;
    idx2pixel_coop2_kernel<<<blocks, threads>>>(coords, vis, out, n);
}